// round 11
// baseline (speedup 1.0000x reference)
#include <cuda_runtime.h>
#include <cuda_fp16.h>
#include <cstdint>

// ---------------- problem constants ----------------
#define S_LEN 2048
#define BATCH 16
#define DIM   1024
#define M_TOT (S_LEN*BATCH)      // 32768
#define N_TOT (3*DIM)            // 3072
#define K_TOT DIM                // 1024

// GEMM tiling (fp16 operands, fp32 accum) — 2 CTAs/SM, BK=64, 4 warps of 64x64
#define BM 128
#define BN 128
#define BK 64
#define KSTEPS (K_TOT/BK)        // 16
#define NSTAGE 3
#define LOOKAHEAD 2
#define THREADS 128
#define SA_BYTES (BM*BK*2)       // 16384 per stage
#define SB_BYTES (BN*BK*2)       // 16384 per stage
#define SMEM_TOTAL (NSTAGE*(SA_BYTES+SB_BYTES))   // 98304 per CTA

// scan partitioning
#define SEGS 64
#define SEGLEN (S_LEN/SEGS)      // 32
#define CH (BATCH*DIM)           // 16384
#define CH2 (CH/2)               // 8192 channel-pairs

// ---------------- device scratch ----------------
__device__ __half g_yact[(size_t)M_TOT * N_TOT]; // activated gates (fp16): tanh(Z), sig(F), sig(O)
__device__ __half g_Xh[(size_t)M_TOT * K_TOT];   // fp16-rounded X
__device__ __half g_Wh[(size_t)N_TOT * K_TOT];   // fp16-rounded W
__device__ float g_seg_a[SEGS*CH];
__device__ float g_seg_c[SEGS*CH];
__device__ float g_seg_s[SEGS*CH];

// ---------------- helpers ----------------
__device__ __forceinline__ uint32_t smem_u32(const void* p) {
    uint32_t a;
    asm("{ .reg .u64 t; cvta.to.shared.u64 t, %1; cvt.u32.u64 %0, t; }" : "=r"(a) : "l"(p));
    return a;
}
__device__ __forceinline__ void cp_async16(uint32_t dst, const void* src) {
    asm volatile("cp.async.cg.shared.global [%0], [%1], 16;" :: "r"(dst), "l"(src) : "memory");
}
__device__ __forceinline__ void cp_commit() {
    asm volatile("cp.async.commit_group;" ::: "memory");
}
__device__ __forceinline__ void cp_wait1() {
    asm volatile("cp.async.wait_group 1;" ::: "memory");
}

__device__ __forceinline__ void ldsm_x4(uint32_t* r, uint32_t addr) {
    asm volatile("ldmatrix.sync.aligned.m8n8.x4.shared.b16 {%0,%1,%2,%3}, [%4];"
        : "=r"(r[0]), "=r"(r[1]), "=r"(r[2]), "=r"(r[3]) : "r"(addr));
}

// mma.sync m16n8k16 fp16 in / fp32 accumulate (baseline PTX, sm_80+)
__device__ __forceinline__ void mma_f16(float* d, const uint32_t* a, uint32_t b0, uint32_t b1) {
    asm volatile(
        "mma.sync.aligned.m16n8k16.row.col.f32.f16.f16.f32 "
        "{%0,%1,%2,%3}, {%4,%5,%6,%7}, {%8,%9}, {%0,%1,%2,%3};"
        : "+f"(d[0]), "+f"(d[1]), "+f"(d[2]), "+f"(d[3])
        : "r"(a[0]), "r"(a[1]), "r"(a[2]), "r"(a[3]), "r"(b0), "r"(b1));
}

__device__ __forceinline__ float fsigmoid(float x) { return 1.0f / (1.0f + __expf(-x)); }
__device__ __forceinline__ float ftanh(float x)    { return 2.0f * fsigmoid(2.0f * x) - 1.0f; }

// smem swizzle for 128B rows (8 x 16B chunks): chunk ^= row&7
__device__ __forceinline__ uint32_t swz_addr(uint32_t base, int row, int chunk) {
    return base + row * 128 + (((uint32_t)(chunk ^ (row & 7))) << 4);
}

// ============================================================
// Kernel 0: fp32 -> fp16 conversion (streamed; float4 in, half4 out)
// ============================================================
__global__ void __launch_bounds__(256)
to_half_pass(const float* __restrict__ src, __half* __restrict__ dst, int n4) {
    int i = blockIdx.x * 256 + threadIdx.x;
    if (i >= n4) return;
    float4 v = ((const float4*)src)[i];
    __half2 h0 = __float22half2_rn(make_float2(v.x, v.y));
    __half2 h1 = __float22half2_rn(make_float2(v.z, v.w));
    uint2 packed = make_uint2(*(uint32_t*)&h0, *(uint32_t*)&h1);
    ((uint2*)dst)[i] = packed;
}

// ============================================================
// Kernel 1: Y = act(X @ W^T + b)  via mma.sync fp16
//   grid = (24, 256), 128 threads (4 warps = 2m x 2n of 64x64 tiles), 2 CTAs/SM
// ============================================================
__global__ void __launch_bounds__(THREADS, 2)
gemm_gates(const float* __restrict__ bias) {
    extern __shared__ char smem[];
    const uint32_t sA0 = smem_u32(smem);                    // 3 stages of A
    const uint32_t sB0 = sA0 + NSTAGE * SA_BYTES;           // 3 stages of B

    const int tid  = threadIdx.x;
    const int lane = tid & 31;
    const int wid  = tid >> 5;          // 0..3
    const int wm   = wid & 1;           // 64-row slice
    const int wn   = wid >> 1;          // 64-col slice
    const int m0   = blockIdx.y * BM;
    const int n0   = blockIdx.x * BN;
    const int gate = blockIdx.x >> 3;   // 0=Z(tanh) 1=F(sig) 2=O(sig)

    float acc[4][8][4];
    #pragma unroll
    for (int i = 0; i < 4; i++)
        #pragma unroll
        for (int j = 0; j < 8; j++)
            #pragma unroll
            for (int c = 0; c < 4; c++) acc[i][j][c] = 0.0f;

    // ---- cp.async fill (16B chunks; 8 per 128B row). A: 8/thr, B: 8/thr ----
    auto issue = [&](int kt, int buf) {
        const uint32_t sA = sA0 + buf * SA_BYTES;
        const uint32_t sB = sB0 + buf * SB_BYTES;
        const __half* xb = g_Xh + (size_t)m0 * K_TOT + kt * BK;
        const __half* wb = g_Wh + (size_t)n0 * K_TOT + kt * BK;
        #pragma unroll
        for (int i = 0; i < 8; i++) {
            int id = tid + i * THREADS;
            int r = id >> 3, c = id & 7;
            cp_async16(swz_addr(sA, r, c), xb + (size_t)r * K_TOT + c * 8);
        }
        #pragma unroll
        for (int i = 0; i < 8; i++) {
            int id = tid + i * THREADS;
            int r = id >> 3, c = id & 7;
            cp_async16(swz_addr(sB, r, c), wb + (size_t)r * K_TOT + c * 8);
        }
        cp_commit();
    };

    // ---- per-lane fragment addressing ----
    const int l15 = lane & 15;
    const int lhi = lane >> 4;                 // 0/1 -> k-lo / k-hi 16B chunk of k16 step
    const int aRowBase = wm * 64 + l15;        // + i*16
    const int bRowBase = wn * 64 + l15;        // + jb*16

    issue(0, 0);
    issue(1, 1);

    for (int kt = 0; kt < KSTEPS; kt++) {
        cp_wait1();                              // group kt complete
        __syncthreads();                         // also WAR-protects issue below
        const int nb = kt + LOOKAHEAD;
        if (nb < KSTEPS) issue(nb, nb % NSTAGE);
        else             cp_commit();            // keep group count consistent

        const int buf = kt % NSTAGE;
        const uint32_t sA = sA0 + buf * SA_BYTES;
        const uint32_t sB = sB0 + buf * SB_BYTES;

        #pragma unroll
        for (int ks = 0; ks < 4; ks++) {         // four k16 steps per BK=64
            const int chunk = ks * 2 + lhi;
            uint32_t a[4][4];
            #pragma unroll
            for (int i = 0; i < 4; i++)
                ldsm_x4(a[i], swz_addr(sA, aRowBase + i * 16, chunk));
            #pragma unroll
            for (int jb = 0; jb < 4; jb++) {
                uint32_t r[4];
                ldsm_x4(r, swz_addr(sB, bRowBase + jb * 16, chunk));
                #pragma unroll
                for (int i = 0; i < 4; i++) {
                    mma_f16(acc[i][jb * 2 + 0], a[i], r[0], r[2]);
                    mma_f16(acc[i][jb * 2 + 1], a[i], r[1], r[3]);
                }
            }
        }
        // no trailing barrier: next iteration's wait+sync covers buffer reuse
    }

    // ---- epilogue: bias + activation, fp16 (half2) stores ----
    const int lrow = lane >> 2, lcol = lane & 3;
    #pragma unroll
    for (int j = 0; j < 8; j++) {
        const int n = n0 + wn * 64 + j * 8 + lcol * 2;   // even
        const float b0 = __ldg(bias + n);
        const float b1 = __ldg(bias + n + 1);
        #pragma unroll
        for (int i = 0; i < 4; i++) {
            const int m = m0 + wm * 64 + i * 16 + lrow;
            float y0 = acc[i][j][0] + b0, y1 = acc[i][j][1] + b1;
            float y2 = acc[i][j][2] + b0, y3 = acc[i][j][3] + b1;
            float2 v0, v1;
            if (gate == 0) {
                v0 = make_float2(ftanh(y0), ftanh(y1));
                v1 = make_float2(ftanh(y2), ftanh(y3));
            } else {
                v0 = make_float2(fsigmoid(y0), fsigmoid(y1));
                v1 = make_float2(fsigmoid(y2), fsigmoid(y3));
            }
            *(__half2*)&g_yact[(size_t)m * N_TOT + n]       = __float22half2_rn(v0);
            *(__half2*)&g_yact[(size_t)(m + 8) * N_TOT + n] = __float22half2_rn(v1);
        }
    }
}

// ============================================================
// Kernel 2: per-segment affine reduction, 2 channels/thread (half2 loads)
//   a = prod(1-f), c = local scan from 0
// ============================================================
__global__ void __launch_bounds__(128)
scan_partial() {
    const int g = blockIdx.x * 128 + threadIdx.x;       // seg*CH2 + ch2
    const int seg = g >> 13;                            // /CH2
    const int ch2 = g & (CH2 - 1);
    const int b = ch2 >> 9, d2 = ch2 & 511;
    const __half2* Y = (const __half2*)g_yact;          // half2 row length N_TOT/2

    float2 a = make_float2(1.0f, 1.0f);
    float2 c = make_float2(0.0f, 0.0f);
    const int t0 = seg * SEGLEN;
    #pragma unroll 4
    for (int t = t0; t < t0 + SEGLEN; t++) {
        size_t rb = (size_t)(t * BATCH + b) * (N_TOT / 2);
        float2 z = __half22float2(Y[rb + d2]);
        float2 f = __half22float2(Y[rb + (DIM / 2) + d2]);
        c.x = fmaf(f.x, z.x - c.x, c.x);
        c.y = fmaf(f.y, z.y - c.y, c.y);
        a.x *= (1.0f - f.x);
        a.y *= (1.0f - f.y);
    }
    *(float2*)&g_seg_a[seg * CH + ch2 * 2] = a;
    *(float2*)&g_seg_c[seg * CH + ch2 * 2] = c;
}

// ============================================================
// Kernel 3: sequential combine over 64 segments; emits segment start states + C_last
// ============================================================
__global__ void __launch_bounds__(128)
scan_combine(const float* __restrict__ hidden, float* __restrict__ c_last) {
    const int ch2 = blockIdx.x * 128 + threadIdx.x;     // 0..CH2
    float2 s = *(const float2*)&hidden[ch2 * 2];
    #pragma unroll
    for (int p = 0; p < SEGS; p++) {
        *(float2*)&g_seg_s[p * CH + ch2 * 2] = s;
        float2 aa = *(const float2*)&g_seg_a[p * CH + ch2 * 2];
        float2 cc = *(const float2*)&g_seg_c[p * CH + ch2 * 2];
        s.x = fmaf(aa.x, s.x, cc.x);
        s.y = fmaf(aa.y, s.y, cc.y);
    }
    *(float2*)&c_last[ch2 * 2] = s;
}

// ============================================================
// Kernel 4: replay segments from start state, write H = sig(O) * C (2 ch/thread)
// ============================================================
__global__ void __launch_bounds__(128)
scan_final(float* __restrict__ H) {
    const int g = blockIdx.x * 128 + threadIdx.x;
    const int seg = g >> 13;
    const int ch2 = g & (CH2 - 1);
    const int b = ch2 >> 9, d2 = ch2 & 511;
    const __half2* Y = (const __half2*)g_yact;

    float2 h = *(const float2*)&g_seg_s[seg * CH + ch2 * 2];
    const int t0 = seg * SEGLEN;
    #pragma unroll 4
    for (int t = t0; t < t0 + SEGLEN; t++) {
        size_t rb = (size_t)(t * BATCH + b) * (N_TOT / 2);
        float2 z = __half22float2(Y[rb + d2]);
        float2 f = __half22float2(Y[rb + (DIM / 2) + d2]);
        float2 o = __half22float2(Y[rb + DIM + d2]);
        h.x = fmaf(f.x, z.x - h.x, h.x);
        h.y = fmaf(f.y, z.y - h.y, h.y);
        float2 out = make_float2(o.x * h.x, o.y * h.y);
        *(float2*)&H[(size_t)(t * BATCH + b) * DIM + d2 * 2] = out;
    }
}

// ============================================================
// launcher
// ============================================================
extern "C" void kernel_launch(void* const* d_in, const int* in_sizes, int n_in,
                              void* d_out, int out_size) {
    const float* X      = (const float*)d_in[0];   // (S,B,D)
    const float* hidden = (const float*)d_in[1];   // (B,D)
    const float* W      = (const float*)d_in[2];   // (3D,D)
    const float* b      = (const float*)d_in[3];   // (3D,)
    float* out = (float*)d_out;                    // H (S,B,D) then C_last (1,B,D)

    __half* xh; cudaGetSymbolAddress((void**)&xh, g_Xh);
    __half* wh; cudaGetSymbolAddress((void**)&wh, g_Wh);

    cudaFuncSetAttribute(gemm_gates, cudaFuncAttributeMaxDynamicSharedMemorySize, SMEM_TOTAL);

    to_half_pass<<<(M_TOT * K_TOT / 4 + 255) / 256, 256>>>(X, xh, M_TOT * K_TOT / 4);
    to_half_pass<<<(N_TOT * K_TOT / 4 + 255) / 256, 256>>>(W, wh, N_TOT * K_TOT / 4);

    dim3 grid(N_TOT / BN, M_TOT / BM);             // (24, 256)
    gemm_gates<<<grid, THREADS, SMEM_TOTAL>>>(b);

    scan_partial<<<SEGS * CH2 / 128, 128>>>();
    scan_combine<<<CH2 / 128, 128>>>(hidden, out + (size_t)M_TOT * DIM);
    scan_final<<<SEGS * CH2 / 128, 128>>>(out);
}

// round 12
// speedup vs baseline: 1.0951x; 1.0951x over previous
#include <cuda_runtime.h>
#include <cuda_fp16.h>
#include <cstdint>

// ---------------- problem constants ----------------
#define S_LEN 2048
#define BATCH 16
#define DIM   1024
#define M_TOT (S_LEN*BATCH)      // 32768
#define N_TOT (3*DIM)            // 3072
#define K_TOT DIM                // 1024

// GEMM tiling (fp16 operands, fp32 accum) — 2 CTAs/SM, BK=64 (R10 best config)
#define BM 128
#define BN 128
#define BK 64
#define KSTEPS (K_TOT/BK)        // 16
#define NSTAGE 3
#define LOOKAHEAD 2
#define THREADS 256
#define SA_BYTES (BM*BK*2)       // 16384 per stage
#define SB_BYTES (BN*BK*2)       // 16384 per stage
#define SMEM_TOTAL (NSTAGE*(SA_BYTES+SB_BYTES))   // 98304 per CTA

// scan partitioning
#define SEGS 64
#define SEGLEN (S_LEN/SEGS)      // 32
#define CH (BATCH*DIM)           // 16384
#define CH2 (CH/2)               // 8192 channel-pairs

// conversion sizes (in float4 units)
#define X4 (M_TOT*K_TOT/4)       // 8388608
#define W4 (N_TOT*K_TOT/4)       // 786432

// ---------------- device scratch ----------------
__device__ __half g_yact[(size_t)M_TOT * N_TOT]; // activated gates (fp16): tanh(Z), sig(F), sig(O)
__device__ __half g_Xh[(size_t)M_TOT * K_TOT];   // fp16-rounded X
__device__ __half g_Wh[(size_t)N_TOT * K_TOT];   // fp16-rounded W
__device__ float g_seg_a[SEGS*CH];
__device__ float g_seg_c[SEGS*CH];
__device__ float g_seg_s[SEGS*CH];

// ---------------- helpers ----------------
__device__ __forceinline__ uint32_t smem_u32(const void* p) {
    uint32_t a;
    asm("{ .reg .u64 t; cvta.to.shared.u64 t, %1; cvt.u32.u64 %0, t; }" : "=r"(a) : "l"(p));
    return a;
}
__device__ __forceinline__ void cp_async16(uint32_t dst, const void* src) {
    asm volatile("cp.async.cg.shared.global [%0], [%1], 16;" :: "r"(dst), "l"(src) : "memory");
}
__device__ __forceinline__ void cp_commit() {
    asm volatile("cp.async.commit_group;" ::: "memory");
}
__device__ __forceinline__ void cp_wait1() {
    asm volatile("cp.async.wait_group 1;" ::: "memory");
}

__device__ __forceinline__ void ldsm_x4(uint32_t* r, uint32_t addr) {
    asm volatile("ldmatrix.sync.aligned.m8n8.x4.shared.b16 {%0,%1,%2,%3}, [%4];"
        : "=r"(r[0]), "=r"(r[1]), "=r"(r[2]), "=r"(r[3]) : "r"(addr));
}

// mma.sync m16n8k16 fp16 in / fp32 accumulate (baseline PTX, sm_80+)
__device__ __forceinline__ void mma_f16(float* d, const uint32_t* a, uint32_t b0, uint32_t b1) {
    asm volatile(
        "mma.sync.aligned.m16n8k16.row.col.f32.f16.f16.f32 "
        "{%0,%1,%2,%3}, {%4,%5,%6,%7}, {%8,%9}, {%0,%1,%2,%3};"
        : "+f"(d[0]), "+f"(d[1]), "+f"(d[2]), "+f"(d[3])
        : "r"(a[0]), "r"(a[1]), "r"(a[2]), "r"(a[3]), "r"(b0), "r"(b1));
}

__device__ __forceinline__ float fsigmoid(float x) { return 1.0f / (1.0f + __expf(-x)); }
__device__ __forceinline__ float ftanh(float x)    { return 2.0f * fsigmoid(2.0f * x) - 1.0f; }

// streaming (evict-first) loads/stores
__device__ __forceinline__ uint32_t ldcs_u32(const uint32_t* p) {
    uint32_t v;
    asm volatile("ld.global.cs.b32 %0, [%1];" : "=r"(v) : "l"(p));
    return v;
}
__device__ __forceinline__ void stcs_f2(float* p, float2 v) {
    asm volatile("st.global.cs.v2.f32 [%0], {%1, %2};" :: "l"(p), "f"(v.x), "f"(v.y));
}

// smem swizzle for 128B rows (8 x 16B chunks): chunk ^= row&7
__device__ __forceinline__ uint32_t swz_addr(uint32_t base, int row, int chunk) {
    return base + row * 128 + (((uint32_t)(chunk ^ (row & 7))) << 4);
}

// ============================================================
// Kernel 0: fp32 -> fp16 conversion for X and W in one launch
// ============================================================
__global__ void __launch_bounds__(256)
to_half_both(const float* __restrict__ X, const float* __restrict__ W) {
    int i = blockIdx.x * 256 + threadIdx.x;
    const float* src;
    uint2* dst;
    int idx;
    if (i < X4) { src = X; dst = (uint2*)g_Xh; idx = i; }
    else if (i < X4 + W4) { src = W; dst = (uint2*)g_Wh; idx = i - X4; }
    else return;
    float4 v = ((const float4*)src)[idx];
    __half2 h0 = __float22half2_rn(make_float2(v.x, v.y));
    __half2 h1 = __float22half2_rn(make_float2(v.z, v.w));
    dst[idx] = make_uint2(*(uint32_t*)&h0, *(uint32_t*)&h1);
}

// ============================================================
// Kernel 1: Y = act(X @ W^T + b)  via mma.sync fp16, fragment double-buffering
//   grid = (24, 256), 256 threads (8 warps = 4m x 2n of 32x64 tiles), 2 CTAs/SM
// ============================================================
__global__ void __launch_bounds__(THREADS, 2)
gemm_gates(const float* __restrict__ bias) {
    extern __shared__ char smem[];
    const uint32_t sA0 = smem_u32(smem);                    // 3 stages of A
    const uint32_t sB0 = sA0 + NSTAGE * SA_BYTES;           // 3 stages of B

    const int tid  = threadIdx.x;
    const int lane = tid & 31;
    const int wid  = tid >> 5;          // 0..7
    const int wm   = wid & 3;           // 32-row slice
    const int wn   = wid >> 2;          // 64-col slice (0..1)
    const int m0   = blockIdx.y * BM;
    const int n0   = blockIdx.x * BN;
    const int gate = blockIdx.x >> 3;   // 0=Z(tanh) 1=F(sig) 2=O(sig)

    float acc[2][8][4];
    #pragma unroll
    for (int i = 0; i < 2; i++)
        #pragma unroll
        for (int j = 0; j < 8; j++)
            #pragma unroll
            for (int c = 0; c < 4; c++) acc[i][j][c] = 0.0f;

    // ---- cp.async fill (16B chunks; 8 per 128B row). A: 4/thr, B: 4/thr ----
    auto issue = [&](int kt, int buf) {
        const uint32_t sA = sA0 + buf * SA_BYTES;
        const uint32_t sB = sB0 + buf * SB_BYTES;
        const __half* xb = g_Xh + (size_t)m0 * K_TOT + kt * BK;
        const __half* wb = g_Wh + (size_t)n0 * K_TOT + kt * BK;
        #pragma unroll
        for (int i = 0; i < 4; i++) {
            int id = tid + i * THREADS;
            int r = id >> 3, c = id & 7;
            cp_async16(swz_addr(sA, r, c), xb + (size_t)r * K_TOT + c * 8);
        }
        #pragma unroll
        for (int i = 0; i < 4; i++) {
            int id = tid + i * THREADS;
            int r = id >> 3, c = id & 7;
            cp_async16(swz_addr(sB, r, c), wb + (size_t)r * K_TOT + c * 8);
        }
        cp_commit();
    };

    // ---- per-lane fragment addressing ----
    const int l15 = lane & 15;
    const int lhi = lane >> 4;                 // 0/1 -> k-lo / k-hi 16B chunk of k16 step
    const int aRowBase = wm * 32 + l15;        // + i*16
    const int bRowBase = wn * 64 + l15;        // + jb*16

    issue(0, 0);
    issue(1, 1);

    // fragment double buffers: a 2x2x4, b 2x4x4  (48 regs)
    uint32_t afr[2][2][4], bfr[2][4][4];

    for (int kt = 0; kt < KSTEPS; kt++) {
        cp_wait1();                              // group kt complete
        __syncthreads();                         // also WAR-protects issue below
        const int nb = kt + LOOKAHEAD;
        if (nb < KSTEPS) issue(nb, nb % NSTAGE);
        else             cp_commit();            // keep group count consistent

        const int buf = kt % NSTAGE;
        const uint32_t sA = sA0 + buf * SA_BYTES;
        const uint32_t sB = sB0 + buf * SB_BYTES;

        // prologue: load fragments of ks=0 into buffer 0
        {
            const int chunk = lhi;
            #pragma unroll
            for (int i = 0; i < 2; i++)
                ldsm_x4(afr[0][i], swz_addr(sA, aRowBase + i * 16, chunk));
            #pragma unroll
            for (int jb = 0; jb < 4; jb++)
                ldsm_x4(bfr[0][jb], swz_addr(sB, bRowBase + jb * 16, chunk));
        }

        #pragma unroll
        for (int ks = 0; ks < 4; ks++) {         // four k16 steps per BK=64
            const int cur = ks & 1, nxt = cur ^ 1;
            if (ks < 3) {                        // prefetch ks+1 fragments
                const int chunk = (ks + 1) * 2 + lhi;
                #pragma unroll
                for (int i = 0; i < 2; i++)
                    ldsm_x4(afr[nxt][i], swz_addr(sA, aRowBase + i * 16, chunk));
                #pragma unroll
                for (int jb = 0; jb < 4; jb++)
                    ldsm_x4(bfr[nxt][jb], swz_addr(sB, bRowBase + jb * 16, chunk));
            }
            #pragma unroll
            for (int jb = 0; jb < 4; jb++) {
                #pragma unroll
                for (int i = 0; i < 2; i++) {
                    mma_f16(acc[i][jb * 2 + 0], afr[cur][i], bfr[cur][jb][0], bfr[cur][jb][2]);
                    mma_f16(acc[i][jb * 2 + 1], afr[cur][i], bfr[cur][jb][1], bfr[cur][jb][3]);
                }
            }
        }
        // no trailing barrier: next iteration's wait+sync covers buffer reuse
    }

    // ---- epilogue: bias + activation, fp16 (half2) stores ----
    const int lrow = lane >> 2, lcol = lane & 3;
    #pragma unroll
    for (int j = 0; j < 8; j++) {
        const int n = n0 + wn * 64 + j * 8 + lcol * 2;   // even
        const float b0 = __ldg(bias + n);
        const float b1 = __ldg(bias + n + 1);
        #pragma unroll
        for (int i = 0; i < 2; i++) {
            const int m = m0 + wm * 32 + i * 16 + lrow;
            float y0 = acc[i][j][0] + b0, y1 = acc[i][j][1] + b1;
            float y2 = acc[i][j][2] + b0, y3 = acc[i][j][3] + b1;
            float2 v0, v1;
            if (gate == 0) {
                v0 = make_float2(ftanh(y0), ftanh(y1));
                v1 = make_float2(ftanh(y2), ftanh(y3));
            } else {
                v0 = make_float2(fsigmoid(y0), fsigmoid(y1));
                v1 = make_float2(fsigmoid(y2), fsigmoid(y3));
            }
            *(__half2*)&g_yact[(size_t)m * N_TOT + n]       = __float22half2_rn(v0);
            *(__half2*)&g_yact[(size_t)(m + 8) * N_TOT + n] = __float22half2_rn(v1);
        }
    }
}

// ============================================================
// Kernel 2: per-segment affine reduction, 2 channels/thread (streaming half2 loads)
//   a = prod(1-f), c = local scan from 0
// ============================================================
__global__ void __launch_bounds__(128)
scan_partial() {
    const int g = blockIdx.x * 128 + threadIdx.x;       // seg*CH2 + ch2
    const int seg = g >> 13;                            // /CH2
    const int ch2 = g & (CH2 - 1);
    const int b = ch2 >> 9, d2 = ch2 & 511;
    const uint32_t* Y = (const uint32_t*)g_yact;        // half2 row length N_TOT/2

    float2 a = make_float2(1.0f, 1.0f);
    float2 c = make_float2(0.0f, 0.0f);
    const int t0 = seg * SEGLEN;
    #pragma unroll 4
    for (int t = t0; t < t0 + SEGLEN; t++) {
        size_t rb = (size_t)(t * BATCH + b) * (N_TOT / 2);
        uint32_t zu = ldcs_u32(Y + rb + d2);
        uint32_t fu = ldcs_u32(Y + rb + (DIM / 2) + d2);
        float2 z = __half22float2(*(__half2*)&zu);
        float2 f = __half22float2(*(__half2*)&fu);
        c.x = fmaf(f.x, z.x - c.x, c.x);
        c.y = fmaf(f.y, z.y - c.y, c.y);
        a.x *= (1.0f - f.x);
        a.y *= (1.0f - f.y);
    }
    *(float2*)&g_seg_a[seg * CH + ch2 * 2] = a;
    *(float2*)&g_seg_c[seg * CH + ch2 * 2] = c;
}

// ============================================================
// Kernel 3: sequential combine over 64 segments; emits segment start states + C_last
// ============================================================
__global__ void __launch_bounds__(128)
scan_combine(const float* __restrict__ hidden, float* __restrict__ c_last) {
    const int ch2 = blockIdx.x * 128 + threadIdx.x;     // 0..CH2
    float2 s = *(const float2*)&hidden[ch2 * 2];
    // prefetch segment 0
    float2 aa = *(const float2*)&g_seg_a[ch2 * 2];
    float2 cc = *(const float2*)&g_seg_c[ch2 * 2];
    #pragma unroll
    for (int p = 0; p < SEGS; p++) {
        *(float2*)&g_seg_s[p * CH + ch2 * 2] = s;
        float2 na, nc;
        if (p + 1 < SEGS) {
            na = *(const float2*)&g_seg_a[(p + 1) * CH + ch2 * 2];
            nc = *(const float2*)&g_seg_c[(p + 1) * CH + ch2 * 2];
        }
        s.x = fmaf(aa.x, s.x, cc.x);
        s.y = fmaf(aa.y, s.y, cc.y);
        aa = na; cc = nc;
    }
    *(float2*)&c_last[ch2 * 2] = s;
}

// ============================================================
// Kernel 4: replay segments from start state, write H = sig(O) * C (streaming)
// ============================================================
__global__ void __launch_bounds__(128)
scan_final(float* __restrict__ H) {
    const int g = blockIdx.x * 128 + threadIdx.x;
    const int seg = g >> 13;
    const int ch2 = g & (CH2 - 1);
    const int b = ch2 >> 9, d2 = ch2 & 511;
    const uint32_t* Y = (const uint32_t*)g_yact;

    float2 h = *(const float2*)&g_seg_s[seg * CH + ch2 * 2];
    const int t0 = seg * SEGLEN;
    #pragma unroll 4
    for (int t = t0; t < t0 + SEGLEN; t++) {
        size_t rb = (size_t)(t * BATCH + b) * (N_TOT / 2);
        uint32_t zu = ldcs_u32(Y + rb + d2);
        uint32_t fu = ldcs_u32(Y + rb + (DIM / 2) + d2);
        uint32_t ou = ldcs_u32(Y + rb + DIM + d2);
        float2 z = __half22float2(*(__half2*)&zu);
        float2 f = __half22float2(*(__half2*)&fu);
        float2 o = __half22float2(*(__half2*)&ou);
        h.x = fmaf(f.x, z.x - h.x, h.x);
        h.y = fmaf(f.y, z.y - h.y, h.y);
        stcs_f2(&H[(size_t)(t * BATCH + b) * DIM + d2 * 2],
                make_float2(o.x * h.x, o.y * h.y));
    }
}

// ============================================================
// launcher
// ============================================================
extern "C" void kernel_launch(void* const* d_in, const int* in_sizes, int n_in,
                              void* d_out, int out_size) {
    const float* X      = (const float*)d_in[0];   // (S,B,D)
    const float* hidden = (const float*)d_in[1];   // (B,D)
    const float* W      = (const float*)d_in[2];   // (3D,D)
    const float* b      = (const float*)d_in[3];   // (3D,)
    float* out = (float*)d_out;                    // H (S,B,D) then C_last (1,B,D)

    cudaFuncSetAttribute(gemm_gates, cudaFuncAttributeMaxDynamicSharedMemorySize, SMEM_TOTAL);

    to_half_both<<<(X4 + W4 + 255) / 256, 256>>>(X, W);

    dim3 grid(N_TOT / BN, M_TOT / BM);             // (24, 256)
    gemm_gates<<<grid, THREADS, SMEM_TOTAL>>>(b);

    scan_partial<<<SEGS * CH2 / 128, 128>>>();
    scan_combine<<<CH2 / 128, 128>>>(hidden, out + (size_t)M_TOT * DIM);
    scan_final<<<SEGS * CH2 / 128, 128>>>(out);
}

// round 13
// speedup vs baseline: 1.1112x; 1.0147x over previous
#include <cuda_runtime.h>
#include <cuda_fp16.h>
#include <cstdint>

// ---------------- problem constants ----------------
#define S_LEN 2048
#define BATCH 16
#define DIM   1024
#define M_TOT (S_LEN*BATCH)      // 32768
#define N_TOT (3*DIM)            // 3072
#define K_TOT DIM                // 1024

// GEMM tiling (fp16 operands, fp32 accum) — 2 CTAs/SM, BK=64 (R10 plateau config)
#define BM 128
#define BN 128
#define BK 64
#define KSTEPS (K_TOT/BK)        // 16
#define NSTAGE 3
#define LOOKAHEAD 2
#define THREADS 256
#define SA_BYTES (BM*BK*2)       // 16384 per stage
#define SB_BYTES (BN*BK*2)       // 16384 per stage
#define SMEM_TOTAL (NSTAGE*(SA_BYTES+SB_BYTES))   // 98304 per CTA

// scan partitioning
#define SEGS 64
#define SEGLEN (S_LEN/SEGS)      // 32
#define CH (BATCH*DIM)           // 16384
#define CH2 (CH/2)               // 8192 channel-pairs

// conversion sizes (in float4 units)
#define X4 (M_TOT*K_TOT/4)       // 8388608
#define W4 (N_TOT*K_TOT/4)       // 786432

// ---------------- device scratch ----------------
__device__ __half g_yact[(size_t)M_TOT * N_TOT]; // activated gates (fp16): tanh(Z), sig(F), sig(O)
__device__ __half g_Xh[(size_t)M_TOT * K_TOT];   // fp16-rounded X
__device__ __half g_Wh[(size_t)N_TOT * K_TOT];   // fp16-rounded W
__device__ float g_seg_a[SEGS*CH];
__device__ float g_seg_c[SEGS*CH];
__device__ float g_seg_s[SEGS*CH];

// ---------------- helpers ----------------
__device__ __forceinline__ uint32_t smem_u32(const void* p) {
    uint32_t a;
    asm("{ .reg .u64 t; cvta.to.shared.u64 t, %1; cvt.u32.u64 %0, t; }" : "=r"(a) : "l"(p));
    return a;
}
__device__ __forceinline__ void cp_async16(uint32_t dst, const void* src) {
    asm volatile("cp.async.cg.shared.global [%0], [%1], 16;" :: "r"(dst), "l"(src) : "memory");
}
__device__ __forceinline__ void cp_commit() {
    asm volatile("cp.async.commit_group;" ::: "memory");
}
__device__ __forceinline__ void cp_wait1() {
    asm volatile("cp.async.wait_group 1;" ::: "memory");
}

__device__ __forceinline__ void ldsm_x4(uint32_t* r, uint32_t addr) {
    asm volatile("ldmatrix.sync.aligned.m8n8.x4.shared.b16 {%0,%1,%2,%3}, [%4];"
        : "=r"(r[0]), "=r"(r[1]), "=r"(r[2]), "=r"(r[3]) : "r"(addr));
}

// mma.sync m16n8k16 fp16 in / fp32 accumulate (baseline PTX, sm_80+)
__device__ __forceinline__ void mma_f16(float* d, const uint32_t* a, uint32_t b0, uint32_t b1) {
    asm volatile(
        "mma.sync.aligned.m16n8k16.row.col.f32.f16.f16.f32 "
        "{%0,%1,%2,%3}, {%4,%5,%6,%7}, {%8,%9}, {%0,%1,%2,%3};"
        : "+f"(d[0]), "+f"(d[1]), "+f"(d[2]), "+f"(d[3])
        : "r"(a[0]), "r"(a[1]), "r"(a[2]), "r"(a[3]), "r"(b0), "r"(b1));
}

__device__ __forceinline__ float fsigmoid(float x) { return 1.0f / (1.0f + __expf(-x)); }
__device__ __forceinline__ float ftanh(float x)    { return 2.0f * fsigmoid(2.0f * x) - 1.0f; }

// streaming (evict-first) loads/stores
__device__ __forceinline__ uint32_t ldcs_u32(const uint32_t* p) {
    uint32_t v;
    asm volatile("ld.global.cs.b32 %0, [%1];" : "=r"(v) : "l"(p));
    return v;
}
__device__ __forceinline__ void stcs_f2(float* p, float2 v) {
    asm volatile("st.global.cs.v2.f32 [%0], {%1, %2};" :: "l"(p), "f"(v.x), "f"(v.y));
}

// smem swizzle for 128B rows (8 x 16B chunks): chunk ^= row&7
__device__ __forceinline__ uint32_t swz_addr(uint32_t base, int row, int chunk) {
    return base + row * 128 + (((uint32_t)(chunk ^ (row & 7))) << 4);
}

// ============================================================
// Kernel 0: fp32 -> fp16 conversion for X and W in one launch
// ============================================================
__global__ void __launch_bounds__(256)
to_half_both(const float* __restrict__ X, const float* __restrict__ W) {
    int i = blockIdx.x * 256 + threadIdx.x;
    const float* src;
    uint2* dst;
    int idx;
    if (i < X4) { src = X; dst = (uint2*)g_Xh; idx = i; }
    else if (i < X4 + W4) { src = W; dst = (uint2*)g_Wh; idx = i - X4; }
    else return;
    float4 v = ((const float4*)src)[idx];
    __half2 h0 = __float22half2_rn(make_float2(v.x, v.y));
    __half2 h1 = __float22half2_rn(make_float2(v.z, v.w));
    dst[idx] = make_uint2(*(uint32_t*)&h0, *(uint32_t*)&h1);
}

// ============================================================
// Kernel 1: Y = act(X @ W^T + b)  via mma.sync fp16 (n_base selects gate range)
//   256 threads (8 warps = 4m x 2n of 32x64 tiles), 2 CTAs/SM
// ============================================================
__global__ void __launch_bounds__(THREADS, 2)
gemm_gates(const float* __restrict__ bias, int n_base) {
    extern __shared__ char smem[];
    const uint32_t sA0 = smem_u32(smem);                    // 3 stages of A
    const uint32_t sB0 = sA0 + NSTAGE * SA_BYTES;           // 3 stages of B

    const int tid  = threadIdx.x;
    const int lane = tid & 31;
    const int wid  = tid >> 5;          // 0..7
    const int wm   = wid & 3;           // 32-row slice
    const int wn   = wid >> 2;          // 64-col slice (0..1)
    const int m0   = blockIdx.y * BM;
    const int nt   = n_base / BN + blockIdx.x;
    const int n0   = nt * BN;
    const int gate = nt >> 3;           // 0=Z(tanh) 1=F(sig) 2=O(sig)

    float acc[2][8][4];
    #pragma unroll
    for (int i = 0; i < 2; i++)
        #pragma unroll
        for (int j = 0; j < 8; j++)
            #pragma unroll
            for (int c = 0; c < 4; c++) acc[i][j][c] = 0.0f;

    // ---- cp.async fill (16B chunks; 8 per 128B row). A: 4/thr, B: 4/thr ----
    auto issue = [&](int kt, int buf) {
        const uint32_t sA = sA0 + buf * SA_BYTES;
        const uint32_t sB = sB0 + buf * SB_BYTES;
        const __half* xb = g_Xh + (size_t)m0 * K_TOT + kt * BK;
        const __half* wb = g_Wh + (size_t)n0 * K_TOT + kt * BK;
        #pragma unroll
        for (int i = 0; i < 4; i++) {
            int id = tid + i * THREADS;
            int r = id >> 3, c = id & 7;
            cp_async16(swz_addr(sA, r, c), xb + (size_t)r * K_TOT + c * 8);
        }
        #pragma unroll
        for (int i = 0; i < 4; i++) {
            int id = tid + i * THREADS;
            int r = id >> 3, c = id & 7;
            cp_async16(swz_addr(sB, r, c), wb + (size_t)r * K_TOT + c * 8);
        }
        cp_commit();
    };

    // ---- per-lane fragment addressing ----
    const int l15 = lane & 15;
    const int lhi = lane >> 4;                 // 0/1 -> k-lo / k-hi 16B chunk of k16 step
    const int aRowBase = wm * 32 + l15;        // + i*16
    const int bRowBase = wn * 64 + l15;        // + jb*16

    issue(0, 0);
    issue(1, 1);

    // fragment double buffers: a 2x2x4, b 2x4x4  (48 regs)
    uint32_t afr[2][2][4], bfr[2][4][4];

    for (int kt = 0; kt < KSTEPS; kt++) {
        cp_wait1();                              // group kt complete
        __syncthreads();                         // also WAR-protects issue below
        const int nb = kt + LOOKAHEAD;
        if (nb < KSTEPS) issue(nb, nb % NSTAGE);
        else             cp_commit();            // keep group count consistent

        const int buf = kt % NSTAGE;
        const uint32_t sA = sA0 + buf * SA_BYTES;
        const uint32_t sB = sB0 + buf * SB_BYTES;

        // prologue: load fragments of ks=0 into buffer 0
        {
            const int chunk = lhi;
            #pragma unroll
            for (int i = 0; i < 2; i++)
                ldsm_x4(afr[0][i], swz_addr(sA, aRowBase + i * 16, chunk));
            #pragma unroll
            for (int jb = 0; jb < 4; jb++)
                ldsm_x4(bfr[0][jb], swz_addr(sB, bRowBase + jb * 16, chunk));
        }

        #pragma unroll
        for (int ks = 0; ks < 4; ks++) {         // four k16 steps per BK=64
            const int cur = ks & 1, nxt = cur ^ 1;
            if (ks < 3) {                        // prefetch ks+1 fragments
                const int chunk = (ks + 1) * 2 + lhi;
                #pragma unroll
                for (int i = 0; i < 2; i++)
                    ldsm_x4(afr[nxt][i], swz_addr(sA, aRowBase + i * 16, chunk));
                #pragma unroll
                for (int jb = 0; jb < 4; jb++)
                    ldsm_x4(bfr[nxt][jb], swz_addr(sB, bRowBase + jb * 16, chunk));
            }
            #pragma unroll
            for (int jb = 0; jb < 4; jb++) {
                #pragma unroll
                for (int i = 0; i < 2; i++) {
                    mma_f16(acc[i][jb * 2 + 0], afr[cur][i], bfr[cur][jb][0], bfr[cur][jb][2]);
                    mma_f16(acc[i][jb * 2 + 1], afr[cur][i], bfr[cur][jb][1], bfr[cur][jb][3]);
                }
            }
        }
        // no trailing barrier: next iteration's wait+sync covers buffer reuse
    }

    // ---- epilogue: bias + activation, fp16 (half2) stores ----
    const int lrow = lane >> 2, lcol = lane & 3;
    #pragma unroll
    for (int j = 0; j < 8; j++) {
        const int n = n0 + wn * 64 + j * 8 + lcol * 2;   // even
        const float b0 = __ldg(bias + n);
        const float b1 = __ldg(bias + n + 1);
        #pragma unroll
        for (int i = 0; i < 2; i++) {
            const int m = m0 + wm * 32 + i * 16 + lrow;
            float y0 = acc[i][j][0] + b0, y1 = acc[i][j][1] + b1;
            float y2 = acc[i][j][2] + b0, y3 = acc[i][j][3] + b1;
            float2 v0, v1;
            if (gate == 0) {
                v0 = make_float2(ftanh(y0), ftanh(y1));
                v1 = make_float2(ftanh(y2), ftanh(y3));
            } else {
                v0 = make_float2(fsigmoid(y0), fsigmoid(y1));
                v1 = make_float2(fsigmoid(y2), fsigmoid(y3));
            }
            *(__half2*)&g_yact[(size_t)m * N_TOT + n]       = __float22half2_rn(v0);
            *(__half2*)&g_yact[(size_t)(m + 8) * N_TOT + n] = __float22half2_rn(v1);
        }
    }
}

// ============================================================
// Kernel 2: per-segment affine reduction, 2 channels/thread (streaming half2 loads)
//   a = prod(1-f), c = local scan from 0   (needs Z,F gates only)
// ============================================================
__global__ void __launch_bounds__(128)
scan_partial() {
    const int g = blockIdx.x * 128 + threadIdx.x;       // seg*CH2 + ch2
    const int seg = g >> 13;                            // /CH2
    const int ch2 = g & (CH2 - 1);
    const int b = ch2 >> 9, d2 = ch2 & 511;
    const uint32_t* Y = (const uint32_t*)g_yact;        // half2 row length N_TOT/2

    float2 a = make_float2(1.0f, 1.0f);
    float2 c = make_float2(0.0f, 0.0f);
    const int t0 = seg * SEGLEN;
    #pragma unroll 4
    for (int t = t0; t < t0 + SEGLEN; t++) {
        size_t rb = (size_t)(t * BATCH + b) * (N_TOT / 2);
        uint32_t zu = ldcs_u32(Y + rb + d2);
        uint32_t fu = ldcs_u32(Y + rb + (DIM / 2) + d2);
        float2 z = __half22float2(*(__half2*)&zu);
        float2 f = __half22float2(*(__half2*)&fu);
        c.x = fmaf(f.x, z.x - c.x, c.x);
        c.y = fmaf(f.y, z.y - c.y, c.y);
        a.x *= (1.0f - f.x);
        a.y *= (1.0f - f.y);
    }
    *(float2*)&g_seg_a[seg * CH + ch2 * 2] = a;
    *(float2*)&g_seg_c[seg * CH + ch2 * 2] = c;
}

// ============================================================
// Kernel 3: sequential combine over 64 segments; emits segment start states + C_last
// ============================================================
__global__ void __launch_bounds__(128)
scan_combine(const float* __restrict__ hidden, float* __restrict__ c_last) {
    const int ch2 = blockIdx.x * 128 + threadIdx.x;     // 0..CH2
    float2 s = *(const float2*)&hidden[ch2 * 2];
    // prefetch segment 0
    float2 aa = *(const float2*)&g_seg_a[ch2 * 2];
    float2 cc = *(const float2*)&g_seg_c[ch2 * 2];
    #pragma unroll
    for (int p = 0; p < SEGS; p++) {
        *(float2*)&g_seg_s[p * CH + ch2 * 2] = s;
        float2 na, nc;
        if (p + 1 < SEGS) {
            na = *(const float2*)&g_seg_a[(p + 1) * CH + ch2 * 2];
            nc = *(const float2*)&g_seg_c[(p + 1) * CH + ch2 * 2];
        }
        s.x = fmaf(aa.x, s.x, cc.x);
        s.y = fmaf(aa.y, s.y, cc.y);
        aa = na; cc = nc;
    }
    *(float2*)&c_last[ch2 * 2] = s;
}

// ============================================================
// Kernel 4: replay segments from start state, write H = sig(O) * C (streaming)
// ============================================================
__global__ void __launch_bounds__(128)
scan_final(float* __restrict__ H) {
    const int g = blockIdx.x * 128 + threadIdx.x;
    const int seg = g >> 13;
    const int ch2 = g & (CH2 - 1);
    const int b = ch2 >> 9, d2 = ch2 & 511;
    const uint32_t* Y = (const uint32_t*)g_yact;

    float2 h = *(const float2*)&g_seg_s[seg * CH + ch2 * 2];
    const int t0 = seg * SEGLEN;
    #pragma unroll 4
    for (int t = t0; t < t0 + SEGLEN; t++) {
        size_t rb = (size_t)(t * BATCH + b) * (N_TOT / 2);
        uint32_t zu = ldcs_u32(Y + rb + d2);
        uint32_t fu = ldcs_u32(Y + rb + (DIM / 2) + d2);
        uint32_t ou = ldcs_u32(Y + rb + DIM + d2);
        float2 z = __half22float2(*(__half2*)&zu);
        float2 f = __half22float2(*(__half2*)&fu);
        float2 o = __half22float2(*(__half2*)&ou);
        h.x = fmaf(f.x, z.x - h.x, h.x);
        h.y = fmaf(f.y, z.y - h.y, h.y);
        stcs_f2(&H[(size_t)(t * BATCH + b) * DIM + d2 * 2],
                make_float2(o.x * h.x, o.y * h.y));
    }
}

// ============================================================
// launcher — fork/join: scans over Z,F overlap gemm(O)
// ============================================================
extern "C" void kernel_launch(void* const* d_in, const int* in_sizes, int n_in,
                              void* d_out, int out_size) {
    const float* X      = (const float*)d_in[0];   // (S,B,D)
    const float* hidden = (const float*)d_in[1];   // (B,D)
    const float* W      = (const float*)d_in[2];   // (3D,D)
    const float* b      = (const float*)d_in[3];   // (3D,)
    float* out = (float*)d_out;                    // H (S,B,D) then C_last (1,B,D)

    static cudaStream_t s2 = nullptr;
    static cudaEvent_t evZF = nullptr, evScan = nullptr;
    if (!s2) {
        cudaStreamCreateWithFlags(&s2, cudaStreamNonBlocking);
        cudaEventCreateWithFlags(&evZF, cudaEventDisableTiming);
        cudaEventCreateWithFlags(&evScan, cudaEventDisableTiming);
        cudaFuncSetAttribute(gemm_gates, cudaFuncAttributeMaxDynamicSharedMemorySize, SMEM_TOTAL);
    }

    to_half_both<<<(X4 + W4 + 255) / 256, 256>>>(X, W);

    // gemm over Z and F gate columns (nt 0..15)
    gemm_gates<<<dim3(16, M_TOT / BM), THREADS, SMEM_TOTAL>>>(b, 0);
    cudaEventRecord(evZF, 0);

    // gemm over O gate columns (nt 16..23) continues on default stream
    gemm_gates<<<dim3(8, M_TOT / BM), THREADS, SMEM_TOTAL>>>(b, 16 * BN);

    // forked stream: scans over Z,F run concurrently with gemm(O)
    cudaStreamWaitEvent(s2, evZF, 0);
    scan_partial<<<SEGS * CH2 / 128, 128, 0, s2>>>();
    scan_combine<<<CH2 / 128, 128, 0, s2>>>(hidden, out + (size_t)M_TOT * DIM);
    cudaEventRecord(evScan, s2);

    // join: scan_final needs O gates (default stream) + segment states (s2)
    cudaStreamWaitEvent(0, evScan, 0);
    scan_final<<<SEGS * CH2 / 128, 128>>>(out);
}